// round 15
// baseline (speedup 1.0000x reference)
#include <cuda_runtime.h>
#include <math.h>

#define NHEADS   16
#define HDIM     64
#define ROT      32
#define BS       8
#define CACHE    4096
#define DMODEL   1024
#define SPLITS   4
#define CHUNK    (CACHE / SPLITS)   // 1024
#define NPAIRS   (BS * NHEADS)      // 128

// Scratch (device globals — no runtime allocation allowed)
__device__ float g_proj[3 * BS * DMODEL];            // qh, kh, vh (proj + bias)
__device__ float g_pl[NPAIRS * SPLITS];              // split partial sum-of-exp
__device__ float g_pacc[NPAIRS * SPLITS * HDIM];     // split partial weighted V
__device__ float g_attn[BS * DMODEL];
__device__ int   g_arrive[NPAIRS];                   // zero-init; reset each use

// ---------------------------------------------------------------------------
// Kernel 1: fused QKV projection (measured-best config).
// 512 threads, 8 cols/block, 2 warps/col, weights-before-staging.
// ---------------------------------------------------------------------------
__global__ void __launch_bounds__(512, 2)
proj_kernel(const float* __restrict__ q,
            const float* __restrict__ WQ, const float* __restrict__ bQ,
            const float* __restrict__ WK, const float* __restrict__ bK,
            const float* __restrict__ WV, const float* __restrict__ bV) {
    __shared__ __align__(16) float sx[BS * DMODEL];
    __shared__ float spart[16][BS];

    int w0 = blockIdx.x * 8;
    int p  = w0 >> 10;
    int o0 = w0 & 1023;
    const float* W    = (p == 0) ? WQ : (p == 1) ? WK : WV;
    const float* bias = (p == 0) ? bQ : (p == 1) ? bK : bV;
    float* Y = g_proj + (size_t)p * BS * DMODEL;

    int tid  = threadIdx.x;
    int warp = tid >> 5, lane = tid & 31;
    int colw = warp >> 1, half = warp & 1;
    int o    = o0 + colw;

    const float4* W4 = (const float4*)(W + (size_t)o * DMODEL);
    const float4* x4 = (const float4*)sx;

    float4 wv[4];
#pragma unroll
    for (int it = 0; it < 4; it++) wv[it] = W4[half * 128 + lane + it * 32];

    {
        const float4* g4 = (const float4*)q;
        float4* s4 = (float4*)sx;
        float4 st[4];
#pragma unroll
        for (int it = 0; it < 4; it++) st[it] = g4[tid + it * 512];
#pragma unroll
        for (int it = 0; it < 4; it++) s4[tid + it * 512] = st[it];
    }
    __syncthreads();

    float acc[BS];
#pragma unroll
    for (int b = 0; b < BS; b++) acc[b] = 0.f;
#pragma unroll
    for (int it = 0; it < 4; it++) {
        int d4 = half * 128 + lane + it * 32;
#pragma unroll
        for (int b = 0; b < BS; b++) {
            float4 xv = x4[b * (DMODEL / 4) + d4];
            acc[b] += wv[it].x * xv.x + wv[it].y * xv.y + wv[it].z * xv.z + wv[it].w * xv.w;
        }
    }
#pragma unroll
    for (int off = 16; off; off >>= 1) {
#pragma unroll
        for (int b = 0; b < BS; b++)
            acc[b] += __shfl_xor_sync(0xffffffffu, acc[b], off);
    }
    if (lane == 0) {
#pragma unroll
        for (int b = 0; b < BS; b++) spart[warp][b] = acc[b];
    }
    __syncthreads();

    if (tid < 64) {
        int c = tid >> 3, b = tid & 7;
        int oc = o0 + c;
        Y[b * DMODEL + oc] = spart[2 * c][b] + spart[2 * c + 1][b] + bias[oc];
    }
}

// ---------------------------------------------------------------------------
// Kernel 2: flash-decode split-K=4 WITH FUSED COMBINE.
// grid (4, 128) = 512 blocks x 256thr.  After each block stores its split
// partial, the last block to arrive for its pair (per-pair atomic counter)
// performs the final combine (incl. the new-token score) and writes g_attn.
// Counter is reset by the combining block -> graph-replay deterministic.
// ---------------------------------------------------------------------------
__global__ void __launch_bounds__(256)
attn_kernel(const float* __restrict__ kc,
            const float* __restrict__ vc) {
    int split = blockIdx.x;
    int pair  = blockIdx.y;
    int b = pair >> 4, h = pair & 15;
    int tid = threadIdx.x;

    __shared__ __align__(16) float s_q[HDIM];
    __shared__ __align__(16) float sm_acc[32][HDIM];
    __shared__ float sm_l[32];
    __shared__ int   s_last;
    __shared__ float swsum[2];

    if (tid < HDIM) {
        int d = tid;
        const float* qb = g_proj + b * DMODEL + h * HDIM;
        float qv = qb[d];
        float qr;
        if (d < ROT) {
            float qp = qb[d ^ 1];
            float invf = __powf(10000.f, -(float)(d >> 1) / 16.f);
            float sn, cs;
            sincosf(4096.f * invf, &sn, &cs);
            qr = (d & 1) ? qv * cs + qp * sn : qv * cs - qp * sn;
        } else {
            qr = qv;
        }
        s_q[d] = qr;
    }
    __syncthreads();

    int lane = tid & 31, warp = tid >> 5;
    int g = lane >> 3, l8 = lane & 7;
    int gid = warp * 4 + g;

    float4 qA = *(const float4*)(s_q + l8 * 4);
    float4 qB = *(const float4*)(s_q + 32 + l8 * 4);

    float invf0 = __powf(10000.f, -(float)(2 * l8) / 16.f);
    float invf1 = __powf(10000.f, -(float)(2 * l8 + 1) / 16.f);

    int i0 = split * CHUNK + warp * 4 + g;
    float s0, c0, s1, c1, sd0, cd0, sd1, cd1;
    sincosf((float)i0 * invf0, &s0, &c0);
    sincosf((float)i0 * invf1, &s1, &c1);
    sincosf(32.f * invf0, &sd0, &cd0);
    sincosf(32.f * invf1, &sd1, &cd1);

    const float4* kbase = (const float4*)(kc + (size_t)(b * NHEADS + h) * CACHE * HDIM);
    const float4* vbase = (const float4*)(vc + (size_t)(b * NHEADS + h) * CACHE * HDIM);

    float l = 0.f;
    float4 accA = make_float4(0.f, 0.f, 0.f, 0.f);
    float4 accB = make_float4(0.f, 0.f, 0.f, 0.f);

#pragma unroll 4
    for (int it = 0; it < CHUNK / 32; it++) {
        size_t row = (size_t)(i0 + it * 32) * (HDIM / 4);
        float4 kA = __ldcs(kbase + row + l8);
        float4 kB = __ldcs(kbase + row + 8 + l8);
        float4 vA = __ldcs(vbase + row + l8);
        float4 vB = __ldcs(vbase + row + 8 + l8);

        {
            float x0 = kA.x, x1 = kA.y, x2 = kA.z, x3 = kA.w;
            kA.x = x0 * c0 - x1 * s0;  kA.y = x1 * c0 + x0 * s0;
            kA.z = x2 * c1 - x3 * s1;  kA.w = x3 * c1 + x2 * s1;
        }
        {
            float t0 = c0 * cd0 - s0 * sd0;  s0 = s0 * cd0 + c0 * sd0;  c0 = t0;
            float t1 = c1 * cd1 - s1 * sd1;  s1 = s1 * cd1 + c1 * sd1;  c1 = t1;
        }

        float p = kA.x * qA.x;
        p = fmaf(kA.y, qA.y, p);  p = fmaf(kA.z, qA.z, p);  p = fmaf(kA.w, qA.w, p);
        p = fmaf(kB.x, qB.x, p);  p = fmaf(kB.y, qB.y, p);
        p = fmaf(kB.z, qB.z, p);  p = fmaf(kB.w, qB.w, p);
        p += __shfl_xor_sync(0xffffffffu, p, 1);
        p += __shfl_xor_sync(0xffffffffu, p, 2);
        p += __shfl_xor_sync(0xffffffffu, p, 4);

        float w = __expf(p * 0.125f);
        l += w;
        accA.x = fmaf(w, vA.x, accA.x);  accA.y = fmaf(w, vA.y, accA.y);
        accA.z = fmaf(w, vA.z, accA.z);  accA.w = fmaf(w, vA.w, accA.w);
        accB.x = fmaf(w, vB.x, accB.x);  accB.y = fmaf(w, vB.y, accB.y);
        accB.z = fmaf(w, vB.z, accB.z);  accB.w = fmaf(w, vB.w, accB.w);
    }

    *(float4*)(&sm_acc[gid][l8 * 4])      = accA;
    *(float4*)(&sm_acc[gid][32 + l8 * 4]) = accB;
    if (l8 == 0) sm_l[gid] = l;
    __syncthreads();

    if (tid < HDIM) {
        int d = tid;
        float num = 0.f;
#pragma unroll
        for (int g2 = 0; g2 < 32; g2++) num += sm_acc[g2][d];
        int idx = pair * SPLITS + split;
        g_pacc[idx * HDIM + d] = num;
        if (d == 0) {
            float L = 0.f;
#pragma unroll
            for (int g2 = 0; g2 < 32; g2++) L += sm_l[g2];
            g_pl[idx] = L;
        }
    }
    __syncthreads();

    // ---- last-block-per-pair does the combine ----
    if (tid == 0) {
        __threadfence();                              // publish partials
        int old = atomicAdd(&g_arrive[pair], 1);
        s_last = (old == SPLITS - 1) ? 1 : 0;
    }
    __syncthreads();
    if (!s_last) return;

    if (tid == 0) {
        g_arrive[pair] = 0;                           // reset for next replay
        __threadfence();                              // acquire others' partials
    }
    __syncthreads();

    {
        int d = tid;                                  // only d<64 active compute
        float qr = 0.f, kr = 0.f, vv = 0.f;
        float pl[SPLITS], pacc[SPLITS];
        if (d < HDIM) {
            const float* qb = g_proj + (0 * BS + b) * DMODEL + h * HDIM;
            const float* kb = g_proj + (1 * BS + b) * DMODEL + h * HDIM;
            const float* vb = g_proj + (2 * BS + b) * DMODEL + h * HDIM;
#pragma unroll
            for (int s = 0; s < SPLITS; s++) pl[s] = g_pl[pair * SPLITS + s];
#pragma unroll
            for (int s = 0; s < SPLITS; s++) pacc[s] = g_pacc[(pair * SPLITS + s) * HDIM + d];
            float qv = qb[d], kv = kb[d];
            vv = vb[d];
            if (d < ROT) {
                float qp = qb[d ^ 1], kp = kb[d ^ 1];
                float invf = __powf(10000.f, -(float)(d >> 1) / 16.f);
                float sn, cs;
                sincosf(4096.f * invf, &sn, &cs);
                if (d & 1) { qr = qv * cs + qp * sn; kr = kv * cs + kp * sn; }
                else       { qr = qv * cs - qp * sn; kr = kv * cs - kp * sn; }
            } else { qr = qv; kr = kv; }
        }

        float r = (d < HDIM) ? qr * kr : 0.f;
        r += __shfl_xor_sync(0xffffffffu, r, 16);
        r += __shfl_xor_sync(0xffffffffu, r, 8);
        r += __shfl_xor_sync(0xffffffffu, r, 4);
        r += __shfl_xor_sync(0xffffffffu, r, 2);
        r += __shfl_xor_sync(0xffffffffu, r, 1);
        if (d < HDIM && (d & 31) == 0) swsum[d >> 5] = r;
        __syncthreads();

        if (d < HDIM) {
            float snew = (swsum[0] + swsum[1]) * 0.125f;
            float en  = __expf(snew);
            float L   = en;
            float num = en * vv;
#pragma unroll
            for (int s = 0; s < SPLITS; s++) { L += pl[s]; num += pacc[s]; }
            g_attn[b * DMODEL + h * HDIM + d] = num / L;
        }
    }
}

// ---------------------------------------------------------------------------
// Kernel 3: output projection.  512 blocks x 256thr, 2 cols/block:
// ALL of WO (4MB) is in flight across the grid at once -> fetch completes in
// ~2 DRAM latency rounds independent of L2 state.
// ---------------------------------------------------------------------------
__global__ void __launch_bounds__(256)
oproj_kernel(const float* __restrict__ WO,
             const float* __restrict__ bO,
             float* __restrict__ out) {
    __shared__ __align__(16) float sx[BS * DMODEL];
    __shared__ float spart0[8][BS], spart1[8][BS];

    int tid  = threadIdx.x;
    int warp = tid >> 5, lane = tid & 31;
    int o0   = blockIdx.x * 2;

    const float4* W4 = (const float4*)WO;
    const float4* x4 = (const float4*)sx;

    // weights first: one float4 per col per thread (covers dims 4t..4t+3)
    float4 wv0 = W4[(size_t)o0 * 256 + tid];
    float4 wv1 = W4[(size_t)(o0 + 1) * 256 + tid];

    // staging: 2048 float4 over 256 threads = 8 each
    {
        const float4* g4 = (const float4*)g_attn;
        float4* s4 = (float4*)sx;
        float4 st[8];
#pragma unroll
        for (int it = 0; it < 8; it++) st[it] = g4[tid + it * 256];
#pragma unroll
        for (int it = 0; it < 8; it++) s4[tid + it * 256] = st[it];
    }
    __syncthreads();

    float acc0[BS], acc1[BS];
#pragma unroll
    for (int b = 0; b < BS; b++) { acc0[b] = 0.f; acc1[b] = 0.f; }
#pragma unroll
    for (int b = 0; b < BS; b++) {
        float4 xv = x4[b * 256 + tid];
        acc0[b] += wv0.x * xv.x + wv0.y * xv.y + wv0.z * xv.z + wv0.w * xv.w;
        acc1[b] += wv1.x * xv.x + wv1.y * xv.y + wv1.z * xv.z + wv1.w * xv.w;
    }
#pragma unroll
    for (int off = 16; off; off >>= 1) {
#pragma unroll
        for (int b = 0; b < BS; b++) {
            acc0[b] += __shfl_xor_sync(0xffffffffu, acc0[b], off);
            acc1[b] += __shfl_xor_sync(0xffffffffu, acc1[b], off);
        }
    }
    if (lane == 0) {
#pragma unroll
        for (int b = 0; b < BS; b++) { spart0[warp][b] = acc0[b]; spart1[warp][b] = acc1[b]; }
    }
    __syncthreads();

    if (tid < 16) {
        int c = tid >> 3, b = tid & 7;
        float v = 0.f;
#pragma unroll
        for (int w = 0; w < 8; w++) v += (c == 0) ? spart0[w][b] : spart1[w][b];
        int oc = o0 + c;
        out[b * DMODEL + oc] = v + bO[oc];
    }
}

// ---------------------------------------------------------------------------
extern "C" void kernel_launch(void* const* d_in, const int* in_sizes, int n_in,
                              void* d_out, int out_size) {
    const float* q  = (const float*)d_in[0];
    const float* kc = (const float*)d_in[1];
    const float* vc = (const float*)d_in[2];
    const float* WQ = (const float*)d_in[3];
    const float* bQ = (const float*)d_in[4];
    const float* WK = (const float*)d_in[5];
    const float* bK = (const float*)d_in[6];
    const float* WV = (const float*)d_in[7];
    const float* bV = (const float*)d_in[8];
    const float* WO = (const float*)d_in[9];
    const float* bO = (const float*)d_in[10];

    proj_kernel<<<384, 512>>>(q, WQ, bQ, WK, bK, WV, bV);
    attn_kernel<<<dim3(SPLITS, NPAIRS), 256>>>(kc, vc);
    oproj_kernel<<<DMODEL / 2, 256>>>(WO, bO, (float*)d_out);
}

// round 16
// speedup vs baseline: 1.1564x; 1.1564x over previous
#include <cuda_runtime.h>
#include <math.h>

#define NHEADS   16
#define HDIM     64
#define ROT      32
#define BS       8
#define CACHE    4096
#define DMODEL   1024
#define SPLITS   4
#define CHUNK    (CACHE / SPLITS)   // 1024
#define NPAIRS   (BS * NHEADS)      // 128
#define KVBLKS   64                  // projKV blocks inside attn grid
#define KVCOLS   32                  // cols per projKV block (64*32 = 2048)

// Scratch (device globals — no runtime allocation allowed)
__device__ float g_proj[3 * BS * DMODEL];            // qh, kh, vh (proj + bias)
__device__ float g_pl[NPAIRS * SPLITS];              // split partial sum-of-exp
__device__ float g_pacc[NPAIRS * SPLITS * HDIM];     // split partial weighted V
__device__ float g_attn[BS * DMODEL];

// ---------------------------------------------------------------------------
// Kernel 1: Q projection only (attn's sole dependency).  128 blocks x 512thr,
// 8 cols/block, 2 warps/col, weights-before-staging (measured-best config).
// ---------------------------------------------------------------------------
__global__ void __launch_bounds__(512, 2)
projQ_kernel(const float* __restrict__ q,
             const float* __restrict__ WQ, const float* __restrict__ bQ) {
    __shared__ __align__(16) float sx[BS * DMODEL];
    __shared__ float spart[16][BS];

    int o0 = blockIdx.x * 8;
    int tid  = threadIdx.x;
    int warp = tid >> 5, lane = tid & 31;
    int colw = warp >> 1, half = warp & 1;
    int o    = o0 + colw;

    const float4* W4 = (const float4*)(WQ + (size_t)o * DMODEL);
    const float4* x4 = (const float4*)sx;

    float4 wv[4];
#pragma unroll
    for (int it = 0; it < 4; it++) wv[it] = W4[half * 128 + lane + it * 32];

    {
        const float4* g4 = (const float4*)q;
        float4* s4 = (float4*)sx;
        float4 st[4];
#pragma unroll
        for (int it = 0; it < 4; it++) st[it] = g4[tid + it * 512];
#pragma unroll
        for (int it = 0; it < 4; it++) s4[tid + it * 512] = st[it];
    }
    __syncthreads();

    float acc[BS];
#pragma unroll
    for (int b = 0; b < BS; b++) acc[b] = 0.f;
#pragma unroll
    for (int it = 0; it < 4; it++) {
        int d4 = half * 128 + lane + it * 32;
#pragma unroll
        for (int b = 0; b < BS; b++) {
            float4 xv = x4[b * (DMODEL / 4) + d4];
            acc[b] += wv[it].x * xv.x + wv[it].y * xv.y + wv[it].z * xv.z + wv[it].w * xv.w;
        }
    }
#pragma unroll
    for (int off = 16; off; off >>= 1) {
#pragma unroll
        for (int b = 0; b < BS; b++)
            acc[b] += __shfl_xor_sync(0xffffffffu, acc[b], off);
    }
    if (lane == 0) {
#pragma unroll
        for (int b = 0; b < BS; b++) spart[warp][b] = acc[b];
    }
    __syncthreads();

    if (tid < 64) {
        int c = tid >> 3, b = tid & 7;
        int oc = o0 + c;
        g_proj[b * DMODEL + oc] = spart[2 * c][b] + spart[2 * c + 1][b] + bQ[oc];
    }
}

// ---------------------------------------------------------------------------
// Kernel 2: flash-decode split-K=4 + co-scheduled K/V projection.
// grid (4, 144) x 256thr:
//   y < 128            -> attention block (split = x, pair = y)
//   y >= 128           -> projKV block id = (y-128)*4 + x  (64 blocks,
//                         32 output cols each; overlapped with attention)
// Single launch -> no fork overhead; single wave at <=4 blocks/SM.
// ---------------------------------------------------------------------------
__global__ void __launch_bounds__(256)
attn_kernel(const float* __restrict__ kc,
            const float* __restrict__ vc,
            const float* __restrict__ q,
            const float* __restrict__ WK, const float* __restrict__ bK,
            const float* __restrict__ WV, const float* __restrict__ bV) {
    int split = blockIdx.x;
    int pair  = blockIdx.y;
    int tid = threadIdx.x;

    __shared__ __align__(16) union {
        struct {
            float s_q[HDIM];
            float sm_acc[32][HDIM];
            float sm_l[32];
        } a;
        struct {
            float sx[BS * DMODEL];
        } p;
    } u;

    if (pair >= NPAIRS) {
        // ================= projKV block =================
        int id = (pair - NPAIRS) * SPLITS + split;       // 0..63
        int base = 1024 + id * KVCOLS;                   // 1024..3040
        int p = base >> 10;                              // 1=K, 2=V
        int o0 = base & 1023;
        const float* W    = (p == 1) ? WK : WV;
        const float* bias = (p == 1) ? bK : bV;
        float* Y = g_proj + (size_t)p * BS * DMODEL;

        // stage q: 2048 float4 over 256 threads
        {
            const float4* g4 = (const float4*)q;
            float4* s4 = (float4*)u.p.sx;
            float4 st[8];
#pragma unroll
            for (int it = 0; it < 8; it++) st[it] = g4[tid + it * 256];
#pragma unroll
            for (int it = 0; it < 8; it++) s4[tid + it * 256] = st[it];
        }
        __syncthreads();

        int warp = tid >> 5, lane = tid & 31;
        const float4* x4 = (const float4*)u.p.sx;

        // each warp owns 4 columns (8 warps x 4 = 32 cols/block)
#pragma unroll
        for (int cc = 0; cc < 4; cc++) {
            int col = o0 + warp * 4 + cc;
            const float4* W4 = (const float4*)(W + (size_t)col * DMODEL);
            float4 wv[8];
#pragma unroll
            for (int it = 0; it < 8; it++) wv[it] = W4[lane + it * 32];
            float acc[BS];
#pragma unroll
            for (int b = 0; b < BS; b++) acc[b] = 0.f;
#pragma unroll
            for (int it = 0; it < 8; it++) {
#pragma unroll
                for (int b = 0; b < BS; b++) {
                    float4 xv = x4[b * 256 + lane + it * 32];
                    acc[b] += wv[it].x * xv.x + wv[it].y * xv.y
                            + wv[it].z * xv.z + wv[it].w * xv.w;
                }
            }
#pragma unroll
            for (int off = 16; off; off >>= 1) {
#pragma unroll
                for (int b = 0; b < BS; b++)
                    acc[b] += __shfl_xor_sync(0xffffffffu, acc[b], off);
            }
            if (lane == 0) {
                float bo = bias[col];
#pragma unroll
                for (int b = 0; b < BS; b++)
                    Y[b * DMODEL + col] = acc[b] + bo;
            }
        }
        return;
    }

    // ================= attention block =================
    int b = pair >> 4, h = pair & 15;

    if (tid < HDIM) {
        int d = tid;
        const float* qb = g_proj + b * DMODEL + h * HDIM;
        float qv = qb[d];
        float qr;
        if (d < ROT) {
            float qp = qb[d ^ 1];
            float invf = __powf(10000.f, -(float)(d >> 1) / 16.f);
            float sn, cs;
            sincosf(4096.f * invf, &sn, &cs);
            qr = (d & 1) ? qv * cs + qp * sn : qv * cs - qp * sn;
        } else {
            qr = qv;
        }
        u.a.s_q[d] = qr;
    }
    __syncthreads();

    int lane = tid & 31, warp = tid >> 5;
    int g = lane >> 3, l8 = lane & 7;
    int gid = warp * 4 + g;

    float4 qA = *(const float4*)(u.a.s_q + l8 * 4);
    float4 qB = *(const float4*)(u.a.s_q + 32 + l8 * 4);

    float invf0 = __powf(10000.f, -(float)(2 * l8) / 16.f);
    float invf1 = __powf(10000.f, -(float)(2 * l8 + 1) / 16.f);

    int i0 = split * CHUNK + warp * 4 + g;
    float s0, c0, s1, c1, sd0, cd0, sd1, cd1;
    sincosf((float)i0 * invf0, &s0, &c0);
    sincosf((float)i0 * invf1, &s1, &c1);
    sincosf(32.f * invf0, &sd0, &cd0);
    sincosf(32.f * invf1, &sd1, &cd1);

    const float4* kbase = (const float4*)(kc + (size_t)(b * NHEADS + h) * CACHE * HDIM);
    const float4* vbase = (const float4*)(vc + (size_t)(b * NHEADS + h) * CACHE * HDIM);

    float l = 0.f;
    float4 accA = make_float4(0.f, 0.f, 0.f, 0.f);
    float4 accB = make_float4(0.f, 0.f, 0.f, 0.f);

#pragma unroll 4
    for (int it = 0; it < CHUNK / 32; it++) {
        size_t row = (size_t)(i0 + it * 32) * (HDIM / 4);
        float4 kA = __ldcs(kbase + row + l8);
        float4 kB = __ldcs(kbase + row + 8 + l8);
        float4 vA = __ldcs(vbase + row + l8);
        float4 vB = __ldcs(vbase + row + 8 + l8);

        {
            float x0 = kA.x, x1 = kA.y, x2 = kA.z, x3 = kA.w;
            kA.x = x0 * c0 - x1 * s0;  kA.y = x1 * c0 + x0 * s0;
            kA.z = x2 * c1 - x3 * s1;  kA.w = x3 * c1 + x2 * s1;
        }
        {
            float t0 = c0 * cd0 - s0 * sd0;  s0 = s0 * cd0 + c0 * sd0;  c0 = t0;
            float t1 = c1 * cd1 - s1 * sd1;  s1 = s1 * cd1 + c1 * sd1;  c1 = t1;
        }

        float p = kA.x * qA.x;
        p = fmaf(kA.y, qA.y, p);  p = fmaf(kA.z, qA.z, p);  p = fmaf(kA.w, qA.w, p);
        p = fmaf(kB.x, qB.x, p);  p = fmaf(kB.y, qB.y, p);
        p = fmaf(kB.z, qB.z, p);  p = fmaf(kB.w, qB.w, p);
        p += __shfl_xor_sync(0xffffffffu, p, 1);
        p += __shfl_xor_sync(0xffffffffu, p, 2);
        p += __shfl_xor_sync(0xffffffffu, p, 4);

        float w = __expf(p * 0.125f);
        l += w;
        accA.x = fmaf(w, vA.x, accA.x);  accA.y = fmaf(w, vA.y, accA.y);
        accA.z = fmaf(w, vA.z, accA.z);  accA.w = fmaf(w, vA.w, accA.w);
        accB.x = fmaf(w, vB.x, accB.x);  accB.y = fmaf(w, vB.y, accB.y);
        accB.z = fmaf(w, vB.z, accB.z);  accB.w = fmaf(w, vB.w, accB.w);
    }

    *(float4*)(&u.a.sm_acc[gid][l8 * 4])      = accA;
    *(float4*)(&u.a.sm_acc[gid][32 + l8 * 4]) = accB;
    if (l8 == 0) u.a.sm_l[gid] = l;
    __syncthreads();

    if (tid < HDIM) {
        int d = tid;
        float num = 0.f;
#pragma unroll
        for (int g2 = 0; g2 < 32; g2++) num += u.a.sm_acc[g2][d];
        int idx = pair * SPLITS + split;
        g_pacc[idx * HDIM + d] = num;
        if (d == 0) {
            float L = 0.f;
#pragma unroll
            for (int g2 = 0; g2 < 32; g2++) L += u.a.sm_l[g2];
            g_pl[idx] = L;
        }
    }
}

// ---------------------------------------------------------------------------
// Kernel 3: combine — batched loads up front, single smem exchange (R13).
// ---------------------------------------------------------------------------
__global__ void combine_kernel() {
    int pair = blockIdx.x;
    int b = pair >> 4, h = pair & 15;
    int d = threadIdx.x;          // 0..63
    int warp = d >> 5;

    __shared__ float swsum[2];

    const float* qb = g_proj + (0 * BS + b) * DMODEL + h * HDIM;
    const float* kb = g_proj + (1 * BS + b) * DMODEL + h * HDIM;
    const float* vb = g_proj + (2 * BS + b) * DMODEL + h * HDIM;

    float pl[SPLITS], pacc[SPLITS];
#pragma unroll
    for (int s = 0; s < SPLITS; s++) pl[s] = g_pl[pair * SPLITS + s];
#pragma unroll
    for (int s = 0; s < SPLITS; s++) pacc[s] = g_pacc[(pair * SPLITS + s) * HDIM + d];
    float qv = qb[d], kv = kb[d], vv = vb[d];
    float qp = 0.f, kp = 0.f;
    if (d < ROT) { qp = qb[d ^ 1]; kp = kb[d ^ 1]; }

    float qr, kr;
    if (d < ROT) {
        float invf = __powf(10000.f, -(float)(d >> 1) / 16.f);
        float sn, cs;
        sincosf(4096.f * invf, &sn, &cs);
        if (d & 1) { qr = qv * cs + qp * sn; kr = kv * cs + kp * sn; }
        else       { qr = qv * cs - qp * sn; kr = kv * cs - kp * sn; }
    } else { qr = qv; kr = kv; }

    float r = qr * kr;
    r += __shfl_xor_sync(0xffffffffu, r, 16);
    r += __shfl_xor_sync(0xffffffffu, r, 8);
    r += __shfl_xor_sync(0xffffffffu, r, 4);
    r += __shfl_xor_sync(0xffffffffu, r, 2);
    r += __shfl_xor_sync(0xffffffffu, r, 1);
    if ((d & 31) == 0) swsum[warp] = r;
    __syncthreads();
    float snew = (swsum[0] + swsum[1]) * 0.125f;

    float en  = __expf(snew);
    float L   = en;
    float num = en * vv;
#pragma unroll
    for (int s = 0; s < SPLITS; s++) { L += pl[s]; num += pacc[s]; }

    g_attn[b * DMODEL + h * HDIM + d] = num / L;
}

// ---------------------------------------------------------------------------
// Kernel 4: output projection.  512 blocks x 256thr, 2 cols/block:
// all of WO (4MB) is in flight across the grid at once.
// ---------------------------------------------------------------------------
__global__ void __launch_bounds__(256)
oproj_kernel(const float* __restrict__ WO,
             const float* __restrict__ bO,
             float* __restrict__ out) {
    __shared__ __align__(16) float sx[BS * DMODEL];
    __shared__ float spart0[8][BS], spart1[8][BS];

    int tid  = threadIdx.x;
    int warp = tid >> 5, lane = tid & 31;
    int o0   = blockIdx.x * 2;

    const float4* W4 = (const float4*)WO;
    const float4* x4 = (const float4*)sx;

    // weights first: one float4 per col per thread
    float4 wv0 = W4[(size_t)o0 * 256 + tid];
    float4 wv1 = W4[(size_t)(o0 + 1) * 256 + tid];

    // staging: 2048 float4 over 256 threads = 8 each
    {
        const float4* g4 = (const float4*)g_attn;
        float4* s4 = (float4*)sx;
        float4 st[8];
#pragma unroll
        for (int it = 0; it < 8; it++) st[it] = g4[tid + it * 256];
#pragma unroll
        for (int it = 0; it < 8; it++) s4[tid + it * 256] = st[it];
    }
    __syncthreads();

    float acc0[BS], acc1[BS];
#pragma unroll
    for (int b = 0; b < BS; b++) { acc0[b] = 0.f; acc1[b] = 0.f; }
#pragma unroll
    for (int b = 0; b < BS; b++) {
        float4 xv = x4[b * 256 + tid];
        acc0[b] += wv0.x * xv.x + wv0.y * xv.y + wv0.z * xv.z + wv0.w * xv.w;
        acc1[b] += wv1.x * xv.x + wv1.y * xv.y + wv1.z * xv.z + wv1.w * xv.w;
    }
#pragma unroll
    for (int off = 16; off; off >>= 1) {
#pragma unroll
        for (int b = 0; b < BS; b++) {
            acc0[b] += __shfl_xor_sync(0xffffffffu, acc0[b], off);
            acc1[b] += __shfl_xor_sync(0xffffffffu, acc1[b], off);
        }
    }
    if (lane == 0) {
#pragma unroll
        for (int b = 0; b < BS; b++) { spart0[warp][b] = acc0[b]; spart1[warp][b] = acc1[b]; }
    }
    __syncthreads();

    if (tid < 16) {
        int c = tid >> 3, b = tid & 7;
        float v = 0.f;
#pragma unroll
        for (int w = 0; w < 8; w++) v += (c == 0) ? spart0[w][b] : spart1[w][b];
        int oc = o0 + c;
        out[b * DMODEL + oc] = v + bO[oc];
    }
}

// ---------------------------------------------------------------------------
extern "C" void kernel_launch(void* const* d_in, const int* in_sizes, int n_in,
                              void* d_out, int out_size) {
    const float* q  = (const float*)d_in[0];
    const float* kc = (const float*)d_in[1];
    const float* vc = (const float*)d_in[2];
    const float* WQ = (const float*)d_in[3];
    const float* bQ = (const float*)d_in[4];
    const float* WK = (const float*)d_in[5];
    const float* bK = (const float*)d_in[6];
    const float* WV = (const float*)d_in[7];
    const float* bV = (const float*)d_in[8];
    const float* WO = (const float*)d_in[9];
    const float* bO = (const float*)d_in[10];

    projQ_kernel<<<DMODEL / 8, 512>>>(q, WQ, bQ);
    attn_kernel<<<dim3(SPLITS, NPAIRS + KVBLKS / SPLITS), 256>>>(kc, vc, q, WK, bK, WV, bV);
    combine_kernel<<<NPAIRS, HDIM>>>();
    oproj_kernel<<<DMODEL / 2, 256>>>(WO, bO, (float*)d_out);
}

// round 17
// speedup vs baseline: 1.1679x; 1.0100x over previous
#include <cuda_runtime.h>
#include <math.h>

#define NHEADS   16
#define HDIM     64
#define ROT      32
#define BS       8
#define CACHE    4096
#define DMODEL   1024
#define SPLITS   4
#define CHUNK    (CACHE / SPLITS)   // 1024
#define NPAIRS   (BS * NHEADS)      // 128
#define KQ       4                  // GEMV k-split factor

// Scratch (device globals — no runtime allocation allowed)
__device__ float g_projp[KQ * 3 * BS * DMODEL];      // per-k-quarter partials
__device__ float g_pl[NPAIRS * SPLITS];              // split partial sum-of-exp
__device__ float g_pacc[NPAIRS * SPLITS * HDIM];     // split partial weighted V
__device__ float g_attn[BS * DMODEL];
__device__ float g_sink;                             // DCE sink; never written

// ---------------------------------------------------------------------------
// Kernel 1: QKV projection, split-K=4.  1536 blocks x 256thr.
// Block (grp, kq): 8 output cols (one per warp), 256-wide k-slice.
// Per thread: 2 weight LDG.128 + 2 staging LDG.128 (tiny latency chain),
// 16 LDS.128, shfl tree.  Partials summed by consumers -> no atomics.
// ---------------------------------------------------------------------------
__global__ void __launch_bounds__(256)
proj_kernel(const float* __restrict__ q,
            const float* __restrict__ WQ,
            const float* __restrict__ WK,
            const float* __restrict__ WV) {
    __shared__ __align__(16) float sx[BS * 256];     // 8KB activation slice

    int bid = blockIdx.x;            // 0..1535
    int grp = bid >> 2, kq = bid & 3;
    int w0  = grp * 8;               // uniform p per block (1024 % 8 == 0)
    int p   = w0 >> 10;
    int o0  = w0 & 1023;
    const float* W = (p == 0) ? WQ : (p == 1) ? WK : WV;

    int tid = threadIdx.x;
    int warp = tid >> 5, lane = tid & 31;
    int o = o0 + warp;

    // weights first: this warp's col, this block's k-slice (256 floats)
    const float4* W4 = (const float4*)(W + (size_t)o * DMODEL + kq * 256);
    float4 wv0 = W4[lane];
    float4 wv1 = W4[lane + 32];

    // stage activation slice: 512 float4 over 256 threads
    {
        const float4* g4 = (const float4*)q;
        float4* s4 = (float4*)sx;
#pragma unroll
        for (int it = 0; it < 2; it++) {
            int idx = tid + it * 256;
            int b = idx >> 6, j = idx & 63;
            s4[idx] = g4[b * 256 + kq * 64 + j];
        }
    }
    __syncthreads();

    const float4* x4 = (const float4*)sx;
    float acc[BS];
#pragma unroll
    for (int b = 0; b < BS; b++) {
        float4 xv0 = x4[b * 64 + lane];
        float4 xv1 = x4[b * 64 + 32 + lane];
        acc[b] = wv0.x * xv0.x + wv0.y * xv0.y + wv0.z * xv0.z + wv0.w * xv0.w
               + wv1.x * xv1.x + wv1.y * xv1.y + wv1.z * xv1.z + wv1.w * xv1.w;
    }
#pragma unroll
    for (int off = 16; off; off >>= 1) {
#pragma unroll
        for (int b = 0; b < BS; b++)
            acc[b] += __shfl_xor_sync(0xffffffffu, acc[b], off);
    }
    if (lane == 0) {
#pragma unroll
        for (int b = 0; b < BS; b++)
            g_projp[((kq * 3 + p) * BS + b) * DMODEL + o] = acc[b];
    }
}

// ---------------------------------------------------------------------------
// Kernel 2: flash-decode split-K=4 (R13 core).  grid (4, 128) x 256thr.
// s_q assembled from the 4 proj partials + bias (two-phase), then roped.
// Tail: each block warms its 8KB slice of WO in L2 (R13-measured-best).
// ---------------------------------------------------------------------------
__global__ void __launch_bounds__(256)
attn_kernel(const float* __restrict__ kc,
            const float* __restrict__ vc,
            const float* __restrict__ WO,
            const float* __restrict__ bQ) {
    int split = blockIdx.x;
    int pair  = blockIdx.y;
    int b = pair >> 4, h = pair & 15;
    int tid = threadIdx.x;

    __shared__ __align__(16) float s_qraw[HDIM];
    __shared__ __align__(16) float s_q[HDIM];
    __shared__ __align__(16) float sm_acc[32][HDIM];
    __shared__ float sm_l[32];

    // phase 1: sum partials + bias
    if (tid < HDIM) {
        int col = h * HDIM + tid;
        float p0 = g_projp[((0 * 3 + 0) * BS + b) * DMODEL + col];
        float p1 = g_projp[((1 * 3 + 0) * BS + b) * DMODEL + col];
        float p2 = g_projp[((2 * 3 + 0) * BS + b) * DMODEL + col];
        float p3 = g_projp[((3 * 3 + 0) * BS + b) * DMODEL + col];
        s_qraw[tid] = p0 + p1 + p2 + p3 + bQ[col];
    }
    __syncthreads();

    // phase 2: rope(q) at position 4096
    if (tid < HDIM) {
        int d = tid;
        float qv = s_qraw[d];
        float qr;
        if (d < ROT) {
            float qp = s_qraw[d ^ 1];
            float invf = __powf(10000.f, -(float)(d >> 1) / 16.f);
            float sn, cs;
            sincosf(4096.f * invf, &sn, &cs);
            qr = (d & 1) ? qv * cs + qp * sn : qv * cs - qp * sn;
        } else {
            qr = qv;
        }
        s_q[d] = qr;
    }
    __syncthreads();

    int lane = tid & 31, warp = tid >> 5;
    int g = lane >> 3, l8 = lane & 7;
    int gid = warp * 4 + g;

    float4 qA = *(const float4*)(s_q + l8 * 4);
    float4 qB = *(const float4*)(s_q + 32 + l8 * 4);

    float invf0 = __powf(10000.f, -(float)(2 * l8) / 16.f);
    float invf1 = __powf(10000.f, -(float)(2 * l8 + 1) / 16.f);

    int i0 = split * CHUNK + warp * 4 + g;
    float s0, c0, s1, c1, sd0, cd0, sd1, cd1;
    sincosf((float)i0 * invf0, &s0, &c0);
    sincosf((float)i0 * invf1, &s1, &c1);
    sincosf(32.f * invf0, &sd0, &cd0);
    sincosf(32.f * invf1, &sd1, &cd1);

    const float4* kbase = (const float4*)(kc + (size_t)(b * NHEADS + h) * CACHE * HDIM);
    const float4* vbase = (const float4*)(vc + (size_t)(b * NHEADS + h) * CACHE * HDIM);

    float l = 0.f;
    float4 accA = make_float4(0.f, 0.f, 0.f, 0.f);
    float4 accB = make_float4(0.f, 0.f, 0.f, 0.f);

#pragma unroll 4
    for (int it = 0; it < CHUNK / 32; it++) {
        size_t row = (size_t)(i0 + it * 32) * (HDIM / 4);
        float4 kA = __ldcs(kbase + row + l8);
        float4 kB = __ldcs(kbase + row + 8 + l8);
        float4 vA = __ldcs(vbase + row + l8);
        float4 vB = __ldcs(vbase + row + 8 + l8);

        {
            float x0 = kA.x, x1 = kA.y, x2 = kA.z, x3 = kA.w;
            kA.x = x0 * c0 - x1 * s0;  kA.y = x1 * c0 + x0 * s0;
            kA.z = x2 * c1 - x3 * s1;  kA.w = x3 * c1 + x2 * s1;
        }
        {
            float t0 = c0 * cd0 - s0 * sd0;  s0 = s0 * cd0 + c0 * sd0;  c0 = t0;
            float t1 = c1 * cd1 - s1 * sd1;  s1 = s1 * cd1 + c1 * sd1;  c1 = t1;
        }

        float p = kA.x * qA.x;
        p = fmaf(kA.y, qA.y, p);  p = fmaf(kA.z, qA.z, p);  p = fmaf(kA.w, qA.w, p);
        p = fmaf(kB.x, qB.x, p);  p = fmaf(kB.y, qB.y, p);
        p = fmaf(kB.z, qB.z, p);  p = fmaf(kB.w, qB.w, p);
        p += __shfl_xor_sync(0xffffffffu, p, 1);
        p += __shfl_xor_sync(0xffffffffu, p, 2);
        p += __shfl_xor_sync(0xffffffffu, p, 4);

        float w = __expf(p * 0.125f);
        l += w;
        accA.x = fmaf(w, vA.x, accA.x);  accA.y = fmaf(w, vA.y, accA.y);
        accA.z = fmaf(w, vA.z, accA.z);  accA.w = fmaf(w, vA.w, accA.w);
        accB.x = fmaf(w, vB.x, accB.x);  accB.y = fmaf(w, vB.y, accB.y);
        accB.z = fmaf(w, vB.z, accB.z);  accB.w = fmaf(w, vB.w, accB.w);
    }

    *(float4*)(&sm_acc[gid][l8 * 4])      = accA;
    *(float4*)(&sm_acc[gid][32 + l8 * 4]) = accB;
    if (l8 == 0) sm_l[gid] = l;
    __syncthreads();

    if (tid < HDIM) {
        int d = tid;
        float num = 0.f;
#pragma unroll
        for (int g2 = 0; g2 < 32; g2++) num += sm_acc[g2][d];
        int idx = pair * SPLITS + split;
        g_pacc[idx * HDIM + d] = num;
        if (d == 0) {
            float L = 0.f;
#pragma unroll
            for (int g2 = 0; g2 < 32; g2++) L += sm_l[g2];
            g_pl[idx] = L;
        }
    }

    // late WO warm (R13): this block's distinct 8KB slice, end of block
    {
        int blk = split * NPAIRS + pair;                 // 0..511
        const float4* w4 = (const float4*)WO + (size_t)blk * 512;
        float4 a = w4[tid];
        float4 c = w4[tid + 256];
        float s = a.x + a.y + a.z + a.w + c.x + c.y + c.z + c.w;
        if (s == 1.2345678e33f) g_sink = s;
    }
}

// ---------------------------------------------------------------------------
// Kernel 3: combine — sums proj partials + biases for k/v/q, merges split
// attn partials, writes g_attn, AND seeds d_out with the output bias
// (oproj then atomicAdds its split-K partials on top).
// ---------------------------------------------------------------------------
__global__ void combine_kernel(const float* __restrict__ bQ,
                               const float* __restrict__ bK,
                               const float* __restrict__ bV,
                               const float* __restrict__ bO,
                               float* __restrict__ out) {
    int pair = blockIdx.x;
    int b = pair >> 4, h = pair & 15;
    int d = threadIdx.x;          // 0..63
    int warp = d >> 5;

    __shared__ float swsum[2];

    int col  = h * HDIM + d;
    int colx = h * HDIM + (d ^ 1);

    // seed output bias (covers all 8x1024 across the 128x64 grid)
    out[b * DMODEL + col] = bO[col];

    // batched loads
    float pl[SPLITS], pacc[SPLITS];
#pragma unroll
    for (int s = 0; s < SPLITS; s++) pl[s] = g_pl[pair * SPLITS + s];
#pragma unroll
    for (int s = 0; s < SPLITS; s++) pacc[s] = g_pacc[(pair * SPLITS + s) * HDIM + d];

    float qv = bQ[col], kv = bK[col], vv = bV[col];
    float qp = 0.f, kp = 0.f;
#pragma unroll
    for (int kq = 0; kq < KQ; kq++) {
        qv += g_projp[((kq * 3 + 0) * BS + b) * DMODEL + col];
        kv += g_projp[((kq * 3 + 1) * BS + b) * DMODEL + col];
        vv += g_projp[((kq * 3 + 2) * BS + b) * DMODEL + col];
    }
    if (d < ROT) {
        qp = bQ[colx]; kp = bK[colx];
#pragma unroll
        for (int kq = 0; kq < KQ; kq++) {
            qp += g_projp[((kq * 3 + 0) * BS + b) * DMODEL + colx];
            kp += g_projp[((kq * 3 + 1) * BS + b) * DMODEL + colx];
        }
    }

    float qr, kr;
    if (d < ROT) {
        float invf = __powf(10000.f, -(float)(d >> 1) / 16.f);
        float sn, cs;
        sincosf(4096.f * invf, &sn, &cs);
        if (d & 1) { qr = qv * cs + qp * sn; kr = kv * cs + kp * sn; }
        else       { qr = qv * cs - qp * sn; kr = kv * cs - kp * sn; }
    } else { qr = qv; kr = kv; }

    float r = qr * kr;
    r += __shfl_xor_sync(0xffffffffu, r, 16);
    r += __shfl_xor_sync(0xffffffffu, r, 8);
    r += __shfl_xor_sync(0xffffffffu, r, 4);
    r += __shfl_xor_sync(0xffffffffu, r, 2);
    r += __shfl_xor_sync(0xffffffffu, r, 1);
    if ((d & 31) == 0) swsum[warp] = r;
    __syncthreads();
    float snew = (swsum[0] + swsum[1]) * 0.125f;

    float en  = __expf(snew);
    float L   = en;
    float num = en * vv;
#pragma unroll
    for (int s = 0; s < SPLITS; s++) { L += pl[s]; num += pacc[s]; }

    g_attn[b * DMODEL + col] = num / L;
}

// ---------------------------------------------------------------------------
// Kernel 4: output projection, split-K=4.  512 blocks x 256thr.
// Block (grp, kq): 8 cols x 256-k slice; atomicAdd partial dots into d_out
// (bias pre-seeded by combine).  WO slice is L2-warm from attn's tail.
// ---------------------------------------------------------------------------
__global__ void __launch_bounds__(256)
oproj_kernel(const float* __restrict__ WO,
             float* __restrict__ out) {
    __shared__ __align__(16) float sx[BS * 256];

    int bid = blockIdx.x;            // 0..511
    int grp = bid >> 2, kq = bid & 3;
    int o0  = grp * 8;

    int tid = threadIdx.x;
    int warp = tid >> 5, lane = tid & 31;
    int o = o0 + warp;

    const float4* W4 = (const float4*)(WO + (size_t)o * DMODEL + kq * 256);
    float4 wv0 = W4[lane];
    float4 wv1 = W4[lane + 32];

    {
        const float4* g4 = (const float4*)g_attn;
        float4* s4 = (float4*)sx;
#pragma unroll
        for (int it = 0; it < 2; it++) {
            int idx = tid + it * 256;
            int b = idx >> 6, j = idx & 63;
            s4[idx] = g4[b * 256 + kq * 64 + j];
        }
    }
    __syncthreads();

    const float4* x4 = (const float4*)sx;
    float acc[BS];
#pragma unroll
    for (int b = 0; b < BS; b++) {
        float4 xv0 = x4[b * 64 + lane];
        float4 xv1 = x4[b * 64 + 32 + lane];
        acc[b] = wv0.x * xv0.x + wv0.y * xv0.y + wv0.z * xv0.z + wv0.w * xv0.w
               + wv1.x * xv1.x + wv1.y * xv1.y + wv1.z * xv1.z + wv1.w * xv1.w;
    }
#pragma unroll
    for (int off = 16; off; off >>= 1) {
#pragma unroll
        for (int b = 0; b < BS; b++)
            acc[b] += __shfl_xor_sync(0xffffffffu, acc[b], off);
    }
    if (lane == 0) {
#pragma unroll
        for (int b = 0; b < BS; b++)
            atomicAdd(&out[b * DMODEL + o], acc[b]);
    }
}

// ---------------------------------------------------------------------------
extern "C" void kernel_launch(void* const* d_in, const int* in_sizes, int n_in,
                              void* d_out, int out_size) {
    const float* q  = (const float*)d_in[0];
    const float* kc = (const float*)d_in[1];
    const float* vc = (const float*)d_in[2];
    const float* WQ = (const float*)d_in[3];
    const float* bQ = (const float*)d_in[4];
    const float* WK = (const float*)d_in[5];
    const float* bK = (const float*)d_in[6];
    const float* WV = (const float*)d_in[7];
    const float* bV = (const float*)d_in[8];
    const float* WO = (const float*)d_in[9];
    const float* bO = (const float*)d_in[10];

    proj_kernel<<<3 * (DMODEL / 8) * KQ, 256>>>(q, WQ, WK, WV);
    attn_kernel<<<dim3(SPLITS, NPAIRS), 256>>>(kc, vc, WO, bQ);
    combine_kernel<<<NPAIRS, HDIM>>>(bQ, bK, bV, bO, (float*)d_out);
    oproj_kernel<<<(DMODEL / 8) * KQ, 256>>>(WO, (float*)d_out);
}